// round 7
// baseline (speedup 1.0000x reference)
#include <cuda_runtime.h>
#include <cuda_bf16.h>
#include <cstdint>

// Problem constants
#define B_SZ 8192
#define K_SZ 32
#define D_SZ 512
#define KA   1024            // A cols: [xh | xl] ; Bop K-range: [Mh ; Ml]
#define ASTRIDE 40           // smem row stride in bf16 halves (conflict-free ldmatrix)
#define SA_HALVES (128 * ASTRIDE)
#define NPART 8              // split-K factor for compute_M

// Scratch (device globals — no allocation allowed)
__device__ float4 g_q2[B_SZ * (D_SZ / 4)];            // 16 MB: q2 = x@M + c
__device__ float  g_c[D_SZ];                          // c = b1 @ w2
__device__ __nv_bfloat16 g_A2[B_SZ * KA];             // 16 MB: [xh | xl]
__device__ __nv_bfloat16 g_Bop[D_SZ * KA];            // 1 MB:  Bop[n][k] = [Mh;Ml] K-major
__device__ float g_MpartT[NPART][D_SZ * D_SZ];        // 8 MB:  partial M, transposed

__device__ __forceinline__ uint32_t smem_u32(const void* p) {
    uint32_t a;
    asm("{ .reg .u64 t; cvta.to.shared.u64 t, %1; cvt.u32.u64 %0, t; }" : "=r"(a) : "l"(p));
    return a;
}

// ---------------------------------------------------------------------------
// Kernel 1a: split-K partial of M: part[z][n][d] = sum_{e in slice z} w1[e,d]w2[e,n]
// ---------------------------------------------------------------------------
__global__ void compute_M_part_kernel(const float* __restrict__ w1,
                                      const float* __restrict__ w2) {
    __shared__ float As[16][64];
    __shared__ float Bs[16][64];
    const int tid = threadIdx.x;
    const int lRow = tid / 16;
    const int lCol = (tid % 16) * 4;
    const int d0 = blockIdx.y * 64;
    const int j0 = blockIdx.x * 64;
    const int e_lo = blockIdx.z * 64;
    const int tRow = (tid / 16) * 4;
    const int tCol = (tid % 16) * 4;

    float acc[4][4] = {};
    for (int e0 = e_lo; e0 < e_lo + 64; e0 += 16) {
        *(float4*)&As[lRow][lCol] = *(const float4*)(w1 + (e0 + lRow) * D_SZ + d0 + lCol);
        *(float4*)&Bs[lRow][lCol] = *(const float4*)(w2 + (e0 + lRow) * D_SZ + j0 + lCol);
        __syncthreads();
#pragma unroll
        for (int e = 0; e < 16; e++) {
            float rm[4], rn[4];
#pragma unroll
            for (int i = 0; i < 4; i++) rm[i] = As[e][tRow + i];
#pragma unroll
            for (int j = 0; j < 4; j++) rn[j] = Bs[e][tCol + j];
#pragma unroll
            for (int i = 0; i < 4; i++)
#pragma unroll
                for (int j = 0; j < 4; j++)
                    acc[i][j] = fmaf(rm[i], rn[j], acc[i][j]);
        }
        __syncthreads();
    }
    float* part = g_MpartT[blockIdx.z];
#pragma unroll
    for (int jj = 0; jj < 4; jj++) {
        const int n = j0 + tCol + jj;
        float4 v = make_float4(acc[0][jj], acc[1][jj], acc[2][jj], acc[3][jj]);
        *(float4*)(part + (size_t)n * D_SZ + d0 + tRow) = v;
    }
}

// ---------------------------------------------------------------------------
// Kernel 1b: reduce partials, split hi/lo, write g_Bop.
// ---------------------------------------------------------------------------
__global__ void reduce_split_kernel() {
    const int idx = blockIdx.x * blockDim.x + threadIdx.x;  // 65536
    const int n = idx >> 7;
    const int d0 = (idx & 127) * 4;
    float4 s = make_float4(0.f, 0.f, 0.f, 0.f);
#pragma unroll
    for (int p = 0; p < NPART; p++) {
        float4 v = *(const float4*)(g_MpartT[p] + (size_t)n * D_SZ + d0);
        s.x += v.x; s.y += v.y; s.z += v.z; s.w += v.w;
    }
    __nv_bfloat16 h4[4], l4[4];
    const float sv[4] = {s.x, s.y, s.z, s.w};
#pragma unroll
    for (int i = 0; i < 4; i++) {
        __nv_bfloat16 h = __float2bfloat16_rn(sv[i]);
        h4[i] = h;
        l4[i] = __float2bfloat16_rn(sv[i] - __bfloat162float(h));
    }
    *(uint2*)(g_Bop + (size_t)n * KA + d0) = *(uint2*)h4;
    *(uint2*)(g_Bop + (size_t)n * KA + 512 + d0) = *(uint2*)l4;
}

// ---------------------------------------------------------------------------
// Kernel 2: split x -> A2 = [xh | xl]; first 8 CTAs also compute c = b1@w2.
// ---------------------------------------------------------------------------
__global__ void split_x_kernel(const float* __restrict__ x,
                               const float* __restrict__ b1,
                               const float* __restrict__ w2) {
    __shared__ float red[256];
    const int t = blockIdx.x * blockDim.x + threadIdx.x;  // 1,048,576 threads
    const int b = t >> 7;
    const int c4 = (t & 127) * 4;
    float4 v = *(const float4*)(x + (size_t)b * D_SZ + c4);
    __nv_bfloat16 hx = __float2bfloat16_rn(v.x), hy = __float2bfloat16_rn(v.y);
    __nv_bfloat16 hz = __float2bfloat16_rn(v.z), hw = __float2bfloat16_rn(v.w);
    __nv_bfloat16 lx = __float2bfloat16_rn(v.x - __bfloat162float(hx));
    __nv_bfloat16 ly = __float2bfloat16_rn(v.y - __bfloat162float(hy));
    __nv_bfloat16 lz = __float2bfloat16_rn(v.z - __bfloat162float(hz));
    __nv_bfloat16 lw = __float2bfloat16_rn(v.w - __bfloat162float(hw));
    __nv_bfloat16* row = g_A2 + (size_t)b * KA;
    uint2 hi, lo;
    ((__nv_bfloat16*)&hi)[0] = hx; ((__nv_bfloat16*)&hi)[1] = hy;
    ((__nv_bfloat16*)&hi)[2] = hz; ((__nv_bfloat16*)&hi)[3] = hw;
    ((__nv_bfloat16*)&lo)[0] = lx; ((__nv_bfloat16*)&lo)[1] = ly;
    ((__nv_bfloat16*)&lo)[2] = lz; ((__nv_bfloat16*)&lo)[3] = lw;
    *(uint2*)(row + c4)       = hi;
    *(uint2*)(row + 512 + c4) = lo;

    // Bias c (CTAs 0-7): c[j] = sum_e b1[e]*w2[e,j]
    if (blockIdx.x < 8) {
        const int tid = threadIdx.x;
        const int j = blockIdx.x * 64 + (tid & 63);
        const int eg = tid >> 6;
        float s = 0.f;
        for (int e = eg * 128; e < eg * 128 + 128; e++)
            s = fmaf(b1[e], w2[e * D_SZ + j], s);
        red[tid] = s;
        __syncthreads();
        if (eg == 0)
            g_c[j] = red[tid] + red[tid + 64] + red[tid + 128] + red[tid + 192];
    }
}

// ---------------------------------------------------------------------------
// Kernel 3: warp-MMA bf16 GEMM: q2 = xh@Mh + xh@Ml + xl@Mh + c
// CTA 128x128, 8 warps, 3-stage cp.async, ONE sync per k-step.
// Loop split: c in [0,16) dual-B (Bh+Bl), c in [16,32) single-B.
// ---------------------------------------------------------------------------
__global__ void __launch_bounds__(256, 2)
gemm_mma_kernel() {
    extern __shared__ __nv_bfloat16 ds[];
    __nv_bfloat16* sA  = ds;
    __nv_bfloat16* sBh = ds + 3 * SA_HALVES;
    __nv_bfloat16* sBl = ds + 6 * SA_HALVES;

    const int tid = threadIdx.x;
    const int lane = tid & 31;
    const int wid = tid >> 5;
    const int m0 = blockIdx.y * 128;
    const int n0 = blockIdx.x * 128;
    const int mbase = (wid & 3) * 32;
    const int nbase = (wid >> 2) * 64;

    const __nv_bfloat16* Ab = g_A2 + (size_t)m0 * KA;
    const __nv_bfloat16* Bb = g_Bop + (size_t)n0 * KA;

    const int lrow0 = tid >> 2;         // 0..63
    const int lcc = (tid & 3) * 8;      // 0,8,16,24 halves

    const int aRow = mbase + (lane & 15);
    const int aCol = (lane >= 16) ? 8 : 0;
    const int bRow = nbase + ((lane >= 16) ? 8 : 0) + (lane & 7);
    const int bCol = ((lane >> 3) & 1) * 8;

    float acc[2][8][4];
#pragma unroll
    for (int mf = 0; mf < 2; mf++)
#pragma unroll
        for (int nf = 0; nf < 8; nf++)
#pragma unroll
            for (int r = 0; r < 4; r++) acc[mf][nf][r] = 0.f;

    const int NSTEP = 32;

    // Always commits (possibly empty) so wait_group counting stays uniform.
#define LOAD_STAGE(buf, c)                                                          \
    do {                                                                            \
        if ((c) < NSTEP) {                                                          \
            const int kb = ((c) & 15) * 32;                                         \
            _Pragma("unroll")                                                       \
            for (int i = 0; i < 2; i++) {                                           \
                int row = lrow0 + i * 64;                                           \
                uint32_t da = smem_u32(&sA[(buf) * SA_HALVES + row * ASTRIDE + lcc]); \
                const void* pa = Ab + (size_t)row * KA + (c) * 32 + lcc;            \
                asm volatile("cp.async.cg.shared.global [%0], [%1], 16;"            \
                             :: "r"(da), "l"(pa) : "memory");                       \
                uint32_t dh = smem_u32(&sBh[(buf) * SA_HALVES + row * ASTRIDE + lcc]); \
                const void* ph = Bb + (size_t)row * KA + kb + lcc;                  \
                asm volatile("cp.async.cg.shared.global [%0], [%1], 16;"            \
                             :: "r"(dh), "l"(ph) : "memory");                       \
                if ((c) < 16) {                                                     \
                    uint32_t dl = smem_u32(&sBl[(buf) * SA_HALVES + row * ASTRIDE + lcc]); \
                    const void* pl = Bb + (size_t)row * KA + 512 + kb + lcc;        \
                    asm volatile("cp.async.cg.shared.global [%0], [%1], 16;"        \
                                 :: "r"(dl), "l"(pl) : "memory");                   \
                }                                                                   \
            }                                                                       \
        }                                                                           \
        asm volatile("cp.async.commit_group;" ::: "memory");                        \
    } while (0)

#define LDMA(dst, base, r, c)                                                       \
    do {                                                                            \
        uint32_t addr = smem_u32(&(base)[buf * SA_HALVES + (r) * ASTRIDE + (c)]);   \
        asm volatile("ldmatrix.sync.aligned.m8n8.x4.shared.b16 {%0,%1,%2,%3}, [%4];" \
                     : "=r"((dst)[0]), "=r"((dst)[1]), "=r"((dst)[2]), "=r"((dst)[3]) \
                     : "r"(addr));                                                  \
    } while (0)

#define MMA_ALL(a, b)                                                               \
    do {                                                                            \
        _Pragma("unroll")                                                           \
        for (int mf = 0; mf < 2; mf++)                                              \
            _Pragma("unroll")                                                       \
            for (int nf = 0; nf < 8; nf++) {                                        \
                asm volatile(                                                       \
                    "mma.sync.aligned.m16n8k16.row.col.f32.bf16.bf16.f32 "          \
                    "{%0,%1,%2,%3}, {%4,%5,%6,%7}, {%8,%9}, {%0,%1,%2,%3};"         \
                    : "+f"(acc[mf][nf][0]), "+f"(acc[mf][nf][1]),                   \
                      "+f"(acc[mf][nf][2]), "+f"(acc[mf][nf][3])                    \
                    : "r"((a)[mf][0]), "r"((a)[mf][1]), "r"((a)[mf][2]), "r"((a)[mf][3]), \
                      "r"((b)[nf >> 1][(nf & 1) * 2]), "r"((b)[nf >> 1][(nf & 1) * 2 + 1])); \
            }                                                                       \
    } while (0)

    LOAD_STAGE(0, 0);
    LOAD_STAGE(1, 1);

    int buf = 0, nb = 2;
    // Phase 1: c in [0,16) — dual-B (xh rows vs Bh and Bl)
    for (int c = 0; c < 16; ++c) {
        asm volatile("cp.async.wait_group 1;" ::: "memory");
        __syncthreads();
        LOAD_STAGE(nb, c + 2);
#pragma unroll
        for (int kf = 0; kf < 2; kf++) {
            uint32_t a[2][4];
            LDMA(a[0], sA, aRow, kf * 16 + aCol);
            LDMA(a[1], sA, aRow + 16, kf * 16 + aCol);
            uint32_t b[4][4];
#pragma unroll
            for (int np = 0; np < 4; np++)
                LDMA(b[np], sBh, bRow + np * 16, kf * 16 + bCol);
            MMA_ALL(a, b);
#pragma unroll
            for (int np = 0; np < 4; np++)
                LDMA(b[np], sBl, bRow + np * 16, kf * 16 + bCol);
            MMA_ALL(a, b);
        }
        buf = (buf == 2) ? 0 : buf + 1;
        nb = (nb == 2) ? 0 : nb + 1;
    }
    // Phase 2: c in [16,32) — single-B (xl rows vs Bh)
    for (int c = 16; c < 32; ++c) {
        asm volatile("cp.async.wait_group 1;" ::: "memory");
        __syncthreads();
        LOAD_STAGE(nb, c + 2);
#pragma unroll
        for (int kf = 0; kf < 2; kf++) {
            uint32_t a[2][4];
            LDMA(a[0], sA, aRow, kf * 16 + aCol);
            LDMA(a[1], sA, aRow + 16, kf * 16 + aCol);
            uint32_t b[4][4];
#pragma unroll
            for (int np = 0; np < 4; np++)
                LDMA(b[np], sBh, bRow + np * 16, kf * 16 + bCol);
            MMA_ALL(a, b);
        }
        buf = (buf == 2) ? 0 : buf + 1;
        nb = (nb == 2) ? 0 : nb + 1;
    }

    // Epilogue: acc + bias -> g_q2
    const int g = lane >> 2;
    const int t4 = lane & 3;
    float* q2p = (float*)g_q2;
#pragma unroll
    for (int mf = 0; mf < 2; mf++) {
#pragma unroll
        for (int nf = 0; nf < 8; nf++) {
            const int col = n0 + nbase + nf * 8 + t4 * 2;
            const float c0 = g_c[col], c1 = g_c[col + 1];
            const int r0 = m0 + mbase + mf * 16 + g;
            float2 v0 = make_float2(acc[mf][nf][0] + c0, acc[mf][nf][1] + c1);
            float2 v1 = make_float2(acc[mf][nf][2] + c0, acc[mf][nf][3] + c1);
            *(float2*)(q2p + (size_t)r0 * D_SZ + col) = v0;
            *(float2*)(q2p + (size_t)(r0 + 8) * D_SZ + col) = v1;
        }
    }
}

// ---------------------------------------------------------------------------
// Kernel 4: attention (unchanged — at 88.7% DRAM roofline)
// ---------------------------------------------------------------------------
__global__ void __launch_bounds__(256)
attn_kernel(const float* __restrict__ x,
            const float* __restrict__ keys,
            const float* __restrict__ values,
            float* __restrict__ out) {
    const int b = blockIdx.x;
    const int tid = threadIdx.x;
    const int lane = tid & 31;
    const int warp = tid >> 5;

    __shared__ float4 q2s[128];
    __shared__ float sc[32];
    __shared__ float attn_s[32];

    if (tid < 128) q2s[tid] = g_q2[b * 128 + tid];
    __syncthreads();

    const float4* K4 = (const float4*)keys;
#pragma unroll
    for (int kk = 0; kk < 4; kk++) {
        const int k = warp * 4 + kk;
        const long base = ((long)b * K_SZ + k) * 128;
        float s = 0.f;
#pragma unroll
        for (int i = 0; i < 4; i++) {
            float4 kv = K4[base + i * 32 + lane];
            float4 qv = q2s[i * 32 + lane];
            s = fmaf(kv.x, qv.x, s);
            s = fmaf(kv.y, qv.y, s);
            s = fmaf(kv.z, qv.z, s);
            s = fmaf(kv.w, qv.w, s);
        }
#pragma unroll
        for (int off = 16; off; off >>= 1)
            s += __shfl_xor_sync(0xffffffffu, s, off);
        if (lane == 0) sc[k] = s * 0.044194173824159216f;  // 1/sqrt(512)
    }
    __syncthreads();

    if (tid < 32) {
        float s = sc[tid];
        float m = s;
#pragma unroll
        for (int off = 16; off; off >>= 1)
            m = fmaxf(m, __shfl_xor_sync(0xffffffffu, m, off));
        float p = __expf(s - m);
        float sum = p;
#pragma unroll
        for (int off = 16; off; off >>= 1)
            sum += __shfl_xor_sync(0xffffffffu, sum, off);
        attn_s[tid] = p / sum;
    }
    __syncthreads();

    const float2* V2 = (const float2*)values;
    const float2* X2 = (const float2*)x;
    float2 acc = make_float2(0.f, 0.f);
    const long vbase = (long)b * K_SZ * 256;
#pragma unroll
    for (int k = 0; k < K_SZ; k++) {
        const float a = attn_s[k];
        float2 v = V2[vbase + k * 256 + tid];
        acc.x = fmaf(a, v.x, acc.x);
        acc.y = fmaf(a, v.y, acc.y);
    }
    float2 xv = X2[(long)b * 256 + tid];
    float2 o;
    o.x = 0.5f * xv.x + 0.5f * acc.x;
    o.y = 0.5f * xv.y + 0.5f * acc.y;
    ((float2*)out)[(long)b * 256 + tid] = o;
}

// ---------------------------------------------------------------------------
extern "C" void kernel_launch(void* const* d_in, const int* in_sizes, int n_in,
                              void* d_out, int out_size) {
    (void)in_sizes; (void)n_in; (void)out_size;
    const float* x      = (const float*)d_in[0];
    const float* keys   = (const float*)d_in[1];
    const float* values = (const float*)d_in[2];
    const float* w1     = (const float*)d_in[3];
    const float* b1     = (const float*)d_in[4];
    const float* w2     = (const float*)d_in[5];
    // d_in[6] = b2: per-row constant in scores -> cancels in softmax.
    float* out = (float*)d_out;

    const int gemm_smem = 9 * SA_HALVES * (int)sizeof(__nv_bfloat16);  // 92160
    cudaFuncSetAttribute(gemm_mma_kernel,
                         cudaFuncAttributeMaxDynamicSharedMemorySize, gemm_smem);

    compute_M_part_kernel<<<dim3(8, 8, 8), 256>>>(w1, w2);
    reduce_split_kernel<<<256, 256>>>();                  // writes g_Bop (bf16 hi/lo)
    split_x_kernel<<<4096, 256>>>(x, b1, w2);             // writes g_A2 + g_c
    gemm_mma_kernel<<<dim3(4, 64), 256, gemm_smem>>>();
    attn_kernel<<<B_SZ, 256>>>(x, keys, values, out);
}

// round 10
// speedup vs baseline: 1.2323x; 1.2323x over previous
#include <cuda_runtime.h>
#include <cuda_bf16.h>
#include <cstdint>

// Problem constants
#define B_SZ 8192
#define K_SZ 32
#define D_SZ 512
#define KA   1024            // A cols: [xh | xl] ; Bop K-range: [Mh ; Ml]
#define ASTRIDE 40           // smem row stride in bf16 halves (conflict-free ldmatrix)
#define SA_HALVES (128 * ASTRIDE)
#define NPART 8              // split-K factor for compute_M

// Scratch (device globals — no allocation allowed)
__device__ float4 g_q2[B_SZ * (D_SZ / 4)];            // 16 MB: q2 = x@M + c
__device__ float  g_c[D_SZ];                          // c = b1 @ w2
__device__ __nv_bfloat16 g_A2[B_SZ * KA];             // 16 MB: [xh | xl]
__device__ __nv_bfloat16 g_Bop[D_SZ * KA];            // 1 MB:  Bop[n][k] = [Mh;Ml] K-major
__device__ float g_MpartT[NPART][D_SZ * D_SZ];        // 8 MB:  partial M, transposed

__device__ __forceinline__ uint32_t smem_u32(const void* p) {
    uint32_t a;
    asm("{ .reg .u64 t; cvta.to.shared.u64 t, %1; cvt.u32.u64 %0, t; }" : "=r"(a) : "l"(p));
    return a;
}

// ---------------------------------------------------------------------------
// Kernel 1a: split-K partial of M: part[z][n][d] = sum_{e in slice z} w1[e,d]w2[e,n]
// ---------------------------------------------------------------------------
__global__ void compute_M_part_kernel(const float* __restrict__ w1,
                                      const float* __restrict__ w2) {
    __shared__ float As[16][64];
    __shared__ float Bs[16][64];
    const int tid = threadIdx.x;
    const int lRow = tid / 16;
    const int lCol = (tid % 16) * 4;
    const int d0 = blockIdx.y * 64;
    const int j0 = blockIdx.x * 64;
    const int e_lo = blockIdx.z * 64;
    const int tRow = (tid / 16) * 4;
    const int tCol = (tid % 16) * 4;

    float acc[4][4] = {};
    for (int e0 = e_lo; e0 < e_lo + 64; e0 += 16) {
        *(float4*)&As[lRow][lCol] = *(const float4*)(w1 + (e0 + lRow) * D_SZ + d0 + lCol);
        *(float4*)&Bs[lRow][lCol] = *(const float4*)(w2 + (e0 + lRow) * D_SZ + j0 + lCol);
        __syncthreads();
#pragma unroll
        for (int e = 0; e < 16; e++) {
            float rm[4], rn[4];
#pragma unroll
            for (int i = 0; i < 4; i++) rm[i] = As[e][tRow + i];
#pragma unroll
            for (int j = 0; j < 4; j++) rn[j] = Bs[e][tCol + j];
#pragma unroll
            for (int i = 0; i < 4; i++)
#pragma unroll
                for (int j = 0; j < 4; j++)
                    acc[i][j] = fmaf(rm[i], rn[j], acc[i][j]);
        }
        __syncthreads();
    }
    float* part = g_MpartT[blockIdx.z];
#pragma unroll
    for (int jj = 0; jj < 4; jj++) {
        const int n = j0 + tCol + jj;
        float4 v = make_float4(acc[0][jj], acc[1][jj], acc[2][jj], acc[3][jj]);
        *(float4*)(part + (size_t)n * D_SZ + d0 + tRow) = v;
    }
}

// ---------------------------------------------------------------------------
// Kernel 1b: reduce partials, split hi/lo, write g_Bop.
// ---------------------------------------------------------------------------
__global__ void reduce_split_kernel() {
    const int idx = blockIdx.x * blockDim.x + threadIdx.x;  // 65536
    const int n = idx >> 7;
    const int d0 = (idx & 127) * 4;
    float4 s = make_float4(0.f, 0.f, 0.f, 0.f);
#pragma unroll
    for (int p = 0; p < NPART; p++) {
        float4 v = *(const float4*)(g_MpartT[p] + (size_t)n * D_SZ + d0);
        s.x += v.x; s.y += v.y; s.z += v.z; s.w += v.w;
    }
    __nv_bfloat16 h4[4], l4[4];
    const float sv[4] = {s.x, s.y, s.z, s.w};
#pragma unroll
    for (int i = 0; i < 4; i++) {
        __nv_bfloat16 h = __float2bfloat16_rn(sv[i]);
        h4[i] = h;
        l4[i] = __float2bfloat16_rn(sv[i] - __bfloat162float(h));
    }
    *(uint2*)(g_Bop + (size_t)n * KA + d0) = *(uint2*)h4;
    *(uint2*)(g_Bop + (size_t)n * KA + 512 + d0) = *(uint2*)l4;
}

// ---------------------------------------------------------------------------
// Kernel 2: split x -> A2 = [xh | xl]; first 8 CTAs also compute c = b1@w2.
// ---------------------------------------------------------------------------
__global__ void split_x_kernel(const float* __restrict__ x,
                               const float* __restrict__ b1,
                               const float* __restrict__ w2) {
    __shared__ float red[256];
    const int t = blockIdx.x * blockDim.x + threadIdx.x;
    const int b = t >> 7;
    const int c4 = (t & 127) * 4;
    float4 v = *(const float4*)(x + (size_t)b * D_SZ + c4);
    __nv_bfloat16 hx = __float2bfloat16_rn(v.x), hy = __float2bfloat16_rn(v.y);
    __nv_bfloat16 hz = __float2bfloat16_rn(v.z), hw = __float2bfloat16_rn(v.w);
    __nv_bfloat16 lx = __float2bfloat16_rn(v.x - __bfloat162float(hx));
    __nv_bfloat16 ly = __float2bfloat16_rn(v.y - __bfloat162float(hy));
    __nv_bfloat16 lz = __float2bfloat16_rn(v.z - __bfloat162float(hz));
    __nv_bfloat16 lw = __float2bfloat16_rn(v.w - __bfloat162float(hw));
    __nv_bfloat16* row = g_A2 + (size_t)b * KA;
    uint2 hi, lo;
    ((__nv_bfloat16*)&hi)[0] = hx; ((__nv_bfloat16*)&hi)[1] = hy;
    ((__nv_bfloat16*)&hi)[2] = hz; ((__nv_bfloat16*)&hi)[3] = hw;
    ((__nv_bfloat16*)&lo)[0] = lx; ((__nv_bfloat16*)&lo)[1] = ly;
    ((__nv_bfloat16*)&lo)[2] = lz; ((__nv_bfloat16*)&lo)[3] = lw;
    *(uint2*)(row + c4)       = hi;
    *(uint2*)(row + 512 + c4) = lo;

    if (blockIdx.x < 8) {
        const int tid = threadIdx.x;
        const int j = blockIdx.x * 64 + (tid & 63);
        const int eg = tid >> 6;
        float s = 0.f;
        for (int e = eg * 128; e < eg * 128 + 128; e++)
            s = fmaf(b1[e], w2[e * D_SZ + j], s);
        red[tid] = s;
        __syncthreads();
        if (eg == 0)
            g_c[j] = red[tid] + red[tid + 64] + red[tid + 128] + red[tid + 192];
    }
}

// ---------------------------------------------------------------------------
// Kernel 3: warp-MMA bf16 GEMM: q2 = xh@Mh + xh@Ml + xl@Mh + c
// EXACT R6-benched mainloop (LOAD before wait_group 2, two syncs per step).
// m_off selects the m-half so two launches can bracket the attn overlap.
// ---------------------------------------------------------------------------
__global__ void __launch_bounds__(256, 2)
gemm_mma_kernel(int m_off) {
    extern __shared__ __nv_bfloat16 ds[];
    __nv_bfloat16* sA  = ds;
    __nv_bfloat16* sBh = ds + 3 * SA_HALVES;
    __nv_bfloat16* sBl = ds + 6 * SA_HALVES;

    const int tid = threadIdx.x;
    const int lane = tid & 31;
    const int wid = tid >> 5;
    const int m0 = (blockIdx.y + m_off) * 128;
    const int n0 = blockIdx.x * 128;
    const int mbase = (wid & 3) * 32;
    const int nbase = (wid >> 2) * 64;

    const __nv_bfloat16* Ab = g_A2 + (size_t)m0 * KA;
    const __nv_bfloat16* Bb = g_Bop + (size_t)n0 * KA;

    const int lrow0 = tid >> 2;
    const int lcc = (tid & 3) * 8;

    const int aRow = mbase + (lane & 15);
    const int aCol = (lane >= 16) ? 8 : 0;
    const int bRow = nbase + ((lane >= 16) ? 8 : 0) + (lane & 7);
    const int bCol = ((lane >> 3) & 1) * 8;

    float acc[2][8][4];
#pragma unroll
    for (int mf = 0; mf < 2; mf++)
#pragma unroll
        for (int nf = 0; nf < 8; nf++)
#pragma unroll
            for (int r = 0; r < 4; r++) acc[mf][nf][r] = 0.f;

    const int NSTEP = 32;

#define LOAD_STAGE(buf, c)                                                          \
    do {                                                                            \
        if ((c) < NSTEP) {                                                          \
            const int kb = ((c) & 15) * 32;                                         \
            _Pragma("unroll")                                                       \
            for (int i = 0; i < 2; i++) {                                           \
                int row = lrow0 + i * 64;                                           \
                uint32_t da = smem_u32(&sA[(buf) * SA_HALVES + row * ASTRIDE + lcc]); \
                const void* pa = Ab + (size_t)row * KA + (c) * 32 + lcc;            \
                asm volatile("cp.async.cg.shared.global [%0], [%1], 16;"            \
                             :: "r"(da), "l"(pa) : "memory");                       \
                uint32_t dh = smem_u32(&sBh[(buf) * SA_HALVES + row * ASTRIDE + lcc]); \
                const void* ph = Bb + (size_t)row * KA + kb + lcc;                  \
                asm volatile("cp.async.cg.shared.global [%0], [%1], 16;"            \
                             :: "r"(dh), "l"(ph) : "memory");                       \
                if ((c) < 16) {                                                     \
                    uint32_t dl = smem_u32(&sBl[(buf) * SA_HALVES + row * ASTRIDE + lcc]); \
                    const void* pl = Bb + (size_t)row * KA + 512 + kb + lcc;        \
                    asm volatile("cp.async.cg.shared.global [%0], [%1], 16;"        \
                                 :: "r"(dl), "l"(pl) : "memory");                   \
                }                                                                   \
            }                                                                       \
        }                                                                           \
        asm volatile("cp.async.commit_group;" ::: "memory");                        \
    } while (0)

    LOAD_STAGE(0, 0);
    LOAD_STAGE(1, 1);

    int buf = 0, nbuf2 = 2;
    for (int c = 0; c < NSTEP; ++c) {
        LOAD_STAGE(nbuf2, c + 2);
        asm volatile("cp.async.wait_group 2;" ::: "memory");
        __syncthreads();

#pragma unroll
        for (int kf = 0; kf < 2; kf++) {
            uint32_t a[2][4];
#pragma unroll
            for (int mf = 0; mf < 2; mf++) {
                uint32_t addr = smem_u32(
                    &sA[buf * SA_HALVES + (aRow + mf * 16) * ASTRIDE + kf * 16 + aCol]);
                asm volatile(
                    "ldmatrix.sync.aligned.m8n8.x4.shared.b16 {%0,%1,%2,%3}, [%4];"
                    : "=r"(a[mf][0]), "=r"(a[mf][1]), "=r"(a[mf][2]), "=r"(a[mf][3])
                    : "r"(addr));
            }
            uint32_t b[4][4];
#pragma unroll
            for (int np = 0; np < 4; np++) {
                uint32_t addr = smem_u32(
                    &sBh[buf * SA_HALVES + (bRow + np * 16) * ASTRIDE + kf * 16 + bCol]);
                asm volatile(
                    "ldmatrix.sync.aligned.m8n8.x4.shared.b16 {%0,%1,%2,%3}, [%4];"
                    : "=r"(b[np][0]), "=r"(b[np][1]), "=r"(b[np][2]), "=r"(b[np][3])
                    : "r"(addr));
            }
#pragma unroll
            for (int mf = 0; mf < 2; mf++)
#pragma unroll
                for (int nf = 0; nf < 8; nf++) {
                    asm volatile(
                        "mma.sync.aligned.m16n8k16.row.col.f32.bf16.bf16.f32 "
                        "{%0,%1,%2,%3}, {%4,%5,%6,%7}, {%8,%9}, {%0,%1,%2,%3};"
                        : "+f"(acc[mf][nf][0]), "+f"(acc[mf][nf][1]),
                          "+f"(acc[mf][nf][2]), "+f"(acc[mf][nf][3])
                        : "r"(a[mf][0]), "r"(a[mf][1]), "r"(a[mf][2]), "r"(a[mf][3]),
                          "r"(b[nf >> 1][(nf & 1) * 2]), "r"(b[nf >> 1][(nf & 1) * 2 + 1]));
                }
            if (c < 16) {
#pragma unroll
                for (int np = 0; np < 4; np++) {
                    uint32_t addr = smem_u32(
                        &sBl[buf * SA_HALVES + (bRow + np * 16) * ASTRIDE + kf * 16 + bCol]);
                    asm volatile(
                        "ldmatrix.sync.aligned.m8n8.x4.shared.b16 {%0,%1,%2,%3}, [%4];"
                        : "=r"(b[np][0]), "=r"(b[np][1]), "=r"(b[np][2]), "=r"(b[np][3])
                        : "r"(addr));
                }
#pragma unroll
                for (int mf = 0; mf < 2; mf++)
#pragma unroll
                    for (int nf = 0; nf < 8; nf++) {
                        asm volatile(
                            "mma.sync.aligned.m16n8k16.row.col.f32.bf16.bf16.f32 "
                            "{%0,%1,%2,%3}, {%4,%5,%6,%7}, {%8,%9}, {%0,%1,%2,%3};"
                            : "+f"(acc[mf][nf][0]), "+f"(acc[mf][nf][1]),
                              "+f"(acc[mf][nf][2]), "+f"(acc[mf][nf][3])
                            : "r"(a[mf][0]), "r"(a[mf][1]), "r"(a[mf][2]), "r"(a[mf][3]),
                              "r"(b[nf >> 1][(nf & 1) * 2]), "r"(b[nf >> 1][(nf & 1) * 2 + 1]));
                    }
            }
        }
        __syncthreads();
        buf = (buf == 2) ? 0 : buf + 1;
        nbuf2 = (nbuf2 == 2) ? 0 : nbuf2 + 1;
    }

    const int g = lane >> 2;
    const int t4 = lane & 3;
    float* q2p = (float*)g_q2;
#pragma unroll
    for (int mf = 0; mf < 2; mf++) {
#pragma unroll
        for (int nf = 0; nf < 8; nf++) {
            const int col = n0 + nbase + nf * 8 + t4 * 2;
            const float c0 = g_c[col], c1 = g_c[col + 1];
            const int r0 = m0 + mbase + mf * 16 + g;
            float2 v0 = make_float2(acc[mf][nf][0] + c0, acc[mf][nf][1] + c1);
            float2 v1 = make_float2(acc[mf][nf][2] + c0, acc[mf][nf][3] + c1);
            *(float2*)(q2p + (size_t)r0 * D_SZ + col) = v0;
            *(float2*)(q2p + (size_t)(r0 + 8) * D_SZ + col) = v1;
        }
    }
}

// ---------------------------------------------------------------------------
// Kernel 4: attention (body unchanged; b_off selects the half)
// ---------------------------------------------------------------------------
__global__ void __launch_bounds__(256)
attn_kernel(const float* __restrict__ x,
            const float* __restrict__ keys,
            const float* __restrict__ values,
            float* __restrict__ out, int b_off) {
    const int b = blockIdx.x + b_off;
    const int tid = threadIdx.x;
    const int lane = tid & 31;
    const int warp = tid >> 5;

    __shared__ float4 q2s[128];
    __shared__ float sc[32];
    __shared__ float attn_s[32];

    if (tid < 128) q2s[tid] = g_q2[b * 128 + tid];
    __syncthreads();

    const float4* K4 = (const float4*)keys;
#pragma unroll
    for (int kk = 0; kk < 4; kk++) {
        const int k = warp * 4 + kk;
        const long base = ((long)b * K_SZ + k) * 128;
        float s = 0.f;
#pragma unroll
        for (int i = 0; i < 4; i++) {
            float4 kv = K4[base + i * 32 + lane];
            float4 qv = q2s[i * 32 + lane];
            s = fmaf(kv.x, qv.x, s);
            s = fmaf(kv.y, qv.y, s);
            s = fmaf(kv.z, qv.z, s);
            s = fmaf(kv.w, qv.w, s);
        }
#pragma unroll
        for (int off = 16; off; off >>= 1)
            s += __shfl_xor_sync(0xffffffffu, s, off);
        if (lane == 0) sc[k] = s * 0.044194173824159216f;  // 1/sqrt(512)
    }
    __syncthreads();

    if (tid < 32) {
        float s = sc[tid];
        float m = s;
#pragma unroll
        for (int off = 16; off; off >>= 1)
            m = fmaxf(m, __shfl_xor_sync(0xffffffffu, m, off));
        float p = __expf(s - m);
        float sum = p;
#pragma unroll
        for (int off = 16; off; off >>= 1)
            sum += __shfl_xor_sync(0xffffffffu, sum, off);
        attn_s[tid] = p / sum;
    }
    __syncthreads();

    const float2* V2 = (const float2*)values;
    const float2* X2 = (const float2*)x;
    float2 acc = make_float2(0.f, 0.f);
    const long vbase = (long)b * K_SZ * 256;
#pragma unroll
    for (int k = 0; k < K_SZ; k++) {
        const float a = attn_s[k];
        float2 v = V2[vbase + k * 256 + tid];
        acc.x = fmaf(a, v.x, acc.x);
        acc.y = fmaf(a, v.y, acc.y);
    }
    float2 xv = X2[(long)b * 256 + tid];
    float2 o;
    o.x = 0.5f * xv.x + 0.5f * acc.x;
    o.y = 0.5f * xv.y + 0.5f * acc.y;
    ((float2*)out)[(long)b * 256 + tid] = o;
}

// ---------------------------------------------------------------------------
extern "C" void kernel_launch(void* const* d_in, const int* in_sizes, int n_in,
                              void* d_out, int out_size) {
    (void)in_sizes; (void)n_in; (void)out_size;
    const float* x      = (const float*)d_in[0];
    const float* keys   = (const float*)d_in[1];
    const float* values = (const float*)d_in[2];
    const float* w1     = (const float*)d_in[3];
    const float* b1     = (const float*)d_in[4];
    const float* w2     = (const float*)d_in[5];
    // d_in[6] = b2: per-row constant in scores -> cancels in softmax.
    float* out = (float*)d_out;

    // One-time stream/event infrastructure (created on the correctness run,
    // which happens before graph capture; no device memory is allocated).
    static cudaStream_t s2 = nullptr;
    static cudaEvent_t evRoot = nullptr, evSplit = nullptr, evG1 = nullptr,
                       evG2 = nullptr, evJoin = nullptr;
    if (!s2) {
        cudaStreamCreateWithFlags(&s2, cudaStreamNonBlocking);
        cudaEventCreateWithFlags(&evRoot, cudaEventDisableTiming);
        cudaEventCreateWithFlags(&evSplit, cudaEventDisableTiming);
        cudaEventCreateWithFlags(&evG1, cudaEventDisableTiming);
        cudaEventCreateWithFlags(&evG2, cudaEventDisableTiming);
        cudaEventCreateWithFlags(&evJoin, cudaEventDisableTiming);
    }

    const int gemm_smem = 9 * SA_HALVES * (int)sizeof(__nv_bfloat16);  // 92160
    cudaFuncSetAttribute(gemm_mma_kernel,
                         cudaFuncAttributeMaxDynamicSharedMemorySize, gemm_smem);

    // Fork s2 off the main (captured) stream.
    cudaEventRecord(evRoot, 0);
    cudaStreamWaitEvent(s2, evRoot, 0);

    // s2: split_x (independent of the M-chain)
    split_x_kernel<<<4096, 256, 0, s2>>>(x, b1, w2);
    cudaEventRecord(evSplit, s2);

    // main: M-chain
    compute_M_part_kernel<<<dim3(8, 8, 8), 256>>>(w1, w2);
    reduce_split_kernel<<<256, 256>>>();

    // gemm needs split_x output too
    cudaStreamWaitEvent(0, evSplit, 0);
    gemm_mma_kernel<<<dim3(4, 32), 256, gemm_smem>>>(0);    // m-blocks 0..31
    cudaEventRecord(evG1, 0);
    gemm_mma_kernel<<<dim3(4, 32), 256, gemm_smem>>>(32);   // m-blocks 32..63
    cudaEventRecord(evG2, 0);

    // s2: attention halves, overlapping gemm half 2
    cudaStreamWaitEvent(s2, evG1, 0);
    attn_kernel<<<4096, 256, 0, s2>>>(x, keys, values, out, 0);
    cudaStreamWaitEvent(s2, evG2, 0);
    attn_kernel<<<4096, 256, 0, s2>>>(x, keys, values, out, 4096);

    // Join s2 back into the captured stream.
    cudaEventRecord(evJoin, s2);
    cudaStreamWaitEvent(0, evJoin, 0);
}

// round 11
// speedup vs baseline: 1.2368x; 1.0036x over previous
#include <cuda_runtime.h>
#include <cuda_bf16.h>
#include <cstdint>

// Problem constants
#define B_SZ 8192
#define K_SZ 32
#define D_SZ 512
#define KA   1024            // A cols: [xh | xl] ; Bop K-range: [Mh ; Ml]
#define ASTRIDE 40           // smem row stride in bf16 halves (conflict-free ldmatrix)
#define SA_HALVES (128 * ASTRIDE)
#define NPART 8              // split-K factor for compute_M
#define Q1ROWS 2048          // rows computed by the split-K lead chunk

// Scratch (device globals — no allocation allowed)
__device__ float4 g_q2[B_SZ * (D_SZ / 4)];            // 16 MB: q2 = x@M + c
__device__ float  g_c[D_SZ];                          // c = b1 @ w2
__device__ __nv_bfloat16 g_A2[B_SZ * KA];             // 16 MB: [xh | xl]
__device__ __nv_bfloat16 g_Bop[D_SZ * KA];            // 1 MB:  Bop[n][k] = [Mh;Ml] K-major
__device__ float g_MpartT[NPART][D_SZ * D_SZ];        // 8 MB:  partial M, transposed
__device__ float g_qpart[4][Q1ROWS * D_SZ];           // 16 MB: split-K partials, rows 0..2047

__device__ __forceinline__ uint32_t smem_u32(const void* p) {
    uint32_t a;
    asm("{ .reg .u64 t; cvta.to.shared.u64 t, %1; cvt.u32.u64 %0, t; }" : "=r"(a) : "l"(p));
    return a;
}

// ---------------------------------------------------------------------------
// Kernel 1a: split-K partial of M: part[z][n][d] = sum_{e in slice z} w1[e,d]w2[e,n]
// ---------------------------------------------------------------------------
__global__ void compute_M_part_kernel(const float* __restrict__ w1,
                                      const float* __restrict__ w2) {
    __shared__ float As[16][64];
    __shared__ float Bs[16][64];
    const int tid = threadIdx.x;
    const int lRow = tid / 16;
    const int lCol = (tid % 16) * 4;
    const int d0 = blockIdx.y * 64;
    const int j0 = blockIdx.x * 64;
    const int e_lo = blockIdx.z * 64;
    const int tRow = (tid / 16) * 4;
    const int tCol = (tid % 16) * 4;

    float acc[4][4] = {};
    for (int e0 = e_lo; e0 < e_lo + 64; e0 += 16) {
        *(float4*)&As[lRow][lCol] = *(const float4*)(w1 + (e0 + lRow) * D_SZ + d0 + lCol);
        *(float4*)&Bs[lRow][lCol] = *(const float4*)(w2 + (e0 + lRow) * D_SZ + j0 + lCol);
        __syncthreads();
#pragma unroll
        for (int e = 0; e < 16; e++) {
            float rm[4], rn[4];
#pragma unroll
            for (int i = 0; i < 4; i++) rm[i] = As[e][tRow + i];
#pragma unroll
            for (int j = 0; j < 4; j++) rn[j] = Bs[e][tCol + j];
#pragma unroll
            for (int i = 0; i < 4; i++)
#pragma unroll
                for (int j = 0; j < 4; j++)
                    acc[i][j] = fmaf(rm[i], rn[j], acc[i][j]);
        }
        __syncthreads();
    }
    float* part = g_MpartT[blockIdx.z];
#pragma unroll
    for (int jj = 0; jj < 4; jj++) {
        const int n = j0 + tCol + jj;
        float4 v = make_float4(acc[0][jj], acc[1][jj], acc[2][jj], acc[3][jj]);
        *(float4*)(part + (size_t)n * D_SZ + d0 + tRow) = v;
    }
}

// ---------------------------------------------------------------------------
// Kernel 1b: reduce partials, split hi/lo, write g_Bop.
// ---------------------------------------------------------------------------
__global__ void reduce_split_kernel() {
    const int idx = blockIdx.x * blockDim.x + threadIdx.x;  // 65536
    const int n = idx >> 7;
    const int d0 = (idx & 127) * 4;
    float4 s = make_float4(0.f, 0.f, 0.f, 0.f);
#pragma unroll
    for (int p = 0; p < NPART; p++) {
        float4 v = *(const float4*)(g_MpartT[p] + (size_t)n * D_SZ + d0);
        s.x += v.x; s.y += v.y; s.z += v.z; s.w += v.w;
    }
    __nv_bfloat16 h4[4], l4[4];
    const float sv[4] = {s.x, s.y, s.z, s.w};
#pragma unroll
    for (int i = 0; i < 4; i++) {
        __nv_bfloat16 h = __float2bfloat16_rn(sv[i]);
        h4[i] = h;
        l4[i] = __float2bfloat16_rn(sv[i] - __bfloat162float(h));
    }
    *(uint2*)(g_Bop + (size_t)n * KA + d0) = *(uint2*)h4;
    *(uint2*)(g_Bop + (size_t)n * KA + 512 + d0) = *(uint2*)l4;
}

// ---------------------------------------------------------------------------
// Kernel 2: split x -> A2 = [xh | xl]; first 8 CTAs also compute c = b1@w2.
// ---------------------------------------------------------------------------
__global__ void split_x_kernel(const float* __restrict__ x,
                               const float* __restrict__ b1,
                               const float* __restrict__ w2) {
    __shared__ float red[256];
    const int t = blockIdx.x * blockDim.x + threadIdx.x;
    const int b = t >> 7;
    const int c4 = (t & 127) * 4;
    float4 v = *(const float4*)(x + (size_t)b * D_SZ + c4);
    __nv_bfloat16 hx = __float2bfloat16_rn(v.x), hy = __float2bfloat16_rn(v.y);
    __nv_bfloat16 hz = __float2bfloat16_rn(v.z), hw = __float2bfloat16_rn(v.w);
    __nv_bfloat16 lx = __float2bfloat16_rn(v.x - __bfloat162float(hx));
    __nv_bfloat16 ly = __float2bfloat16_rn(v.y - __bfloat162float(hy));
    __nv_bfloat16 lz = __float2bfloat16_rn(v.z - __bfloat162float(hz));
    __nv_bfloat16 lw = __float2bfloat16_rn(v.w - __bfloat162float(hw));
    __nv_bfloat16* row = g_A2 + (size_t)b * KA;
    uint2 hi, lo;
    ((__nv_bfloat16*)&hi)[0] = hx; ((__nv_bfloat16*)&hi)[1] = hy;
    ((__nv_bfloat16*)&hi)[2] = hz; ((__nv_bfloat16*)&hi)[3] = hw;
    ((__nv_bfloat16*)&lo)[0] = lx; ((__nv_bfloat16*)&lo)[1] = ly;
    ((__nv_bfloat16*)&lo)[2] = lz; ((__nv_bfloat16*)&lo)[3] = lw;
    *(uint2*)(row + c4)       = hi;
    *(uint2*)(row + 512 + c4) = lo;

    if (blockIdx.x < 8) {
        const int tid = threadIdx.x;
        const int j = blockIdx.x * 64 + (tid & 63);
        const int eg = tid >> 6;
        float s = 0.f;
        for (int e = eg * 128; e < eg * 128 + 128; e++)
            s = fmaf(b1[e], w2[e * D_SZ + j], s);
        red[tid] = s;
        __syncthreads();
        if (eg == 0)
            g_c[j] = red[tid] + red[tid + 64] + red[tid + 128] + red[tid + 192];
    }
}

// ---------------------------------------------------------------------------
// Kernel 3: warp-MMA bf16 GEMM: q2 = xh@Mh + xh@Ml + xl@Mh (+ c if !kspl)
// R6-benched mainloop. kspl=1: blockIdx.z selects k-slice [z*8, z*8+8),
// raw partials -> g_qpart[z]. kspl=0: full k, bias added, -> g_q2.
// ---------------------------------------------------------------------------
__global__ void __launch_bounds__(256, 2)
gemm_mma_kernel(int m_off, int kspl) {
    extern __shared__ __nv_bfloat16 ds[];
    __nv_bfloat16* sA  = ds;
    __nv_bfloat16* sBh = ds + 3 * SA_HALVES;
    __nv_bfloat16* sBl = ds + 6 * SA_HALVES;

    const int tid = threadIdx.x;
    const int lane = tid & 31;
    const int wid = tid >> 5;
    const int m0 = (blockIdx.y + m_off) * 128;
    const int n0 = blockIdx.x * 128;
    const int mbase = (wid & 3) * 32;
    const int nbase = (wid >> 2) * 64;

    int cBeg = 0, cEnd = 32;
    float* dst = (float*)g_q2;
    if (kspl) {
        const int z = blockIdx.z;
        cBeg = z * 8;
        cEnd = cBeg + 8;
        dst = g_qpart[z];
    }

    const __nv_bfloat16* Ab = g_A2 + (size_t)m0 * KA;
    const __nv_bfloat16* Bb = g_Bop + (size_t)n0 * KA;

    const int lrow0 = tid >> 2;
    const int lcc = (tid & 3) * 8;

    const int aRow = mbase + (lane & 15);
    const int aCol = (lane >= 16) ? 8 : 0;
    const int bRow = nbase + ((lane >= 16) ? 8 : 0) + (lane & 7);
    const int bCol = ((lane >> 3) & 1) * 8;

    float acc[2][8][4];
#pragma unroll
    for (int mf = 0; mf < 2; mf++)
#pragma unroll
        for (int nf = 0; nf < 8; nf++)
#pragma unroll
            for (int r = 0; r < 4; r++) acc[mf][nf][r] = 0.f;

#define LOAD_STAGE(buf, c)                                                          \
    do {                                                                            \
        if ((c) < cEnd) {                                                           \
            const int kb = ((c) & 15) * 32;                                         \
            _Pragma("unroll")                                                       \
            for (int i = 0; i < 2; i++) {                                           \
                int row = lrow0 + i * 64;                                           \
                uint32_t da = smem_u32(&sA[(buf) * SA_HALVES + row * ASTRIDE + lcc]); \
                const void* pa = Ab + (size_t)row * KA + (c) * 32 + lcc;            \
                asm volatile("cp.async.cg.shared.global [%0], [%1], 16;"            \
                             :: "r"(da), "l"(pa) : "memory");                       \
                uint32_t dh = smem_u32(&sBh[(buf) * SA_HALVES + row * ASTRIDE + lcc]); \
                const void* ph = Bb + (size_t)row * KA + kb + lcc;                  \
                asm volatile("cp.async.cg.shared.global [%0], [%1], 16;"            \
                             :: "r"(dh), "l"(ph) : "memory");                       \
                if ((c) < 16) {                                                     \
                    uint32_t dl = smem_u32(&sBl[(buf) * SA_HALVES + row * ASTRIDE + lcc]); \
                    const void* pl = Bb + (size_t)row * KA + 512 + kb + lcc;        \
                    asm volatile("cp.async.cg.shared.global [%0], [%1], 16;"        \
                                 :: "r"(dl), "l"(pl) : "memory");                   \
                }                                                                   \
            }                                                                       \
        }                                                                           \
        asm volatile("cp.async.commit_group;" ::: "memory");                        \
    } while (0)

    LOAD_STAGE(0, cBeg);
    LOAD_STAGE(1, cBeg + 1);

    int buf = 0, nbuf2 = 2;
    for (int c = cBeg; c < cEnd; ++c) {
        LOAD_STAGE(nbuf2, c + 2);
        asm volatile("cp.async.wait_group 2;" ::: "memory");
        __syncthreads();

#pragma unroll
        for (int kf = 0; kf < 2; kf++) {
            uint32_t a[2][4];
#pragma unroll
            for (int mf = 0; mf < 2; mf++) {
                uint32_t addr = smem_u32(
                    &sA[buf * SA_HALVES + (aRow + mf * 16) * ASTRIDE + kf * 16 + aCol]);
                asm volatile(
                    "ldmatrix.sync.aligned.m8n8.x4.shared.b16 {%0,%1,%2,%3}, [%4];"
                    : "=r"(a[mf][0]), "=r"(a[mf][1]), "=r"(a[mf][2]), "=r"(a[mf][3])
                    : "r"(addr));
            }
            uint32_t b[4][4];
#pragma unroll
            for (int np = 0; np < 4; np++) {
                uint32_t addr = smem_u32(
                    &sBh[buf * SA_HALVES + (bRow + np * 16) * ASTRIDE + kf * 16 + bCol]);
                asm volatile(
                    "ldmatrix.sync.aligned.m8n8.x4.shared.b16 {%0,%1,%2,%3}, [%4];"
                    : "=r"(b[np][0]), "=r"(b[np][1]), "=r"(b[np][2]), "=r"(b[np][3])
                    : "r"(addr));
            }
#pragma unroll
            for (int mf = 0; mf < 2; mf++)
#pragma unroll
                for (int nf = 0; nf < 8; nf++) {
                    asm volatile(
                        "mma.sync.aligned.m16n8k16.row.col.f32.bf16.bf16.f32 "
                        "{%0,%1,%2,%3}, {%4,%5,%6,%7}, {%8,%9}, {%0,%1,%2,%3};"
                        : "+f"(acc[mf][nf][0]), "+f"(acc[mf][nf][1]),
                          "+f"(acc[mf][nf][2]), "+f"(acc[mf][nf][3])
                        : "r"(a[mf][0]), "r"(a[mf][1]), "r"(a[mf][2]), "r"(a[mf][3]),
                          "r"(b[nf >> 1][(nf & 1) * 2]), "r"(b[nf >> 1][(nf & 1) * 2 + 1]));
                }
            if (c < 16) {
#pragma unroll
                for (int np = 0; np < 4; np++) {
                    uint32_t addr = smem_u32(
                        &sBl[buf * SA_HALVES + (bRow + np * 16) * ASTRIDE + kf * 16 + bCol]);
                    asm volatile(
                        "ldmatrix.sync.aligned.m8n8.x4.shared.b16 {%0,%1,%2,%3}, [%4];"
                        : "=r"(b[np][0]), "=r"(b[np][1]), "=r"(b[np][2]), "=r"(b[np][3])
                        : "r"(addr));
                }
#pragma unroll
                for (int mf = 0; mf < 2; mf++)
#pragma unroll
                    for (int nf = 0; nf < 8; nf++) {
                        asm volatile(
                            "mma.sync.aligned.m16n8k16.row.col.f32.bf16.bf16.f32 "
                            "{%0,%1,%2,%3}, {%4,%5,%6,%7}, {%8,%9}, {%0,%1,%2,%3};"
                            : "+f"(acc[mf][nf][0]), "+f"(acc[mf][nf][1]),
                              "+f"(acc[mf][nf][2]), "+f"(acc[mf][nf][3])
                            : "r"(a[mf][0]), "r"(a[mf][1]), "r"(a[mf][2]), "r"(a[mf][3]),
                              "r"(b[nf >> 1][(nf & 1) * 2]), "r"(b[nf >> 1][(nf & 1) * 2 + 1]));
                    }
            }
        }
        __syncthreads();
        buf = (buf == 2) ? 0 : buf + 1;
        nbuf2 = (nbuf2 == 2) ? 0 : nbuf2 + 1;
    }

    // Epilogue (bias only for the full-k path)
    const float bmul = kspl ? 0.f : 1.f;
    const int g = lane >> 2;
    const int t4 = lane & 3;
#pragma unroll
    for (int mf = 0; mf < 2; mf++) {
#pragma unroll
        for (int nf = 0; nf < 8; nf++) {
            const int col = n0 + nbase + nf * 8 + t4 * 2;
            const float c0 = g_c[col] * bmul, c1 = g_c[col + 1] * bmul;
            const int r0 = m0 + mbase + mf * 16 + g;
            float2 v0 = make_float2(acc[mf][nf][0] + c0, acc[mf][nf][1] + c1);
            float2 v1 = make_float2(acc[mf][nf][2] + c0, acc[mf][nf][3] + c1);
            *(float2*)(dst + (size_t)r0 * D_SZ + col) = v0;
            *(float2*)(dst + (size_t)(r0 + 8) * D_SZ + col) = v1;
        }
    }
}

// ---------------------------------------------------------------------------
// Kernel 3b: sum the 4 k-slice partials + bias -> q2 rows [0, Q1ROWS)
// ---------------------------------------------------------------------------
__global__ void reduce_q1_kernel() {
    const int idx = blockIdx.x * blockDim.x + threadIdx.x;  // 262144
    const int row = idx >> 7;
    const int c4 = (idx & 127) * 4;
    const size_t off = (size_t)row * D_SZ + c4;
    float4 s = *(const float4*)(g_qpart[0] + off);
    float4 v1 = *(const float4*)(g_qpart[1] + off);
    float4 v2 = *(const float4*)(g_qpart[2] + off);
    float4 v3 = *(const float4*)(g_qpart[3] + off);
    float4 cb = *(const float4*)(g_c + c4);
    s.x += v1.x + v2.x + v3.x + cb.x;
    s.y += v1.y + v2.y + v3.y + cb.y;
    s.z += v1.z + v2.z + v3.z + cb.z;
    s.w += v1.w + v2.w + v3.w + cb.w;
    *(float4*)((float*)g_q2 + off) = s;
}

// ---------------------------------------------------------------------------
// Kernel 4: attention (body unchanged; b_off selects the chunk)
// ---------------------------------------------------------------------------
__global__ void __launch_bounds__(256)
attn_kernel(const float* __restrict__ x,
            const float* __restrict__ keys,
            const float* __restrict__ values,
            float* __restrict__ out, int b_off) {
    const int b = blockIdx.x + b_off;
    const int tid = threadIdx.x;
    const int lane = tid & 31;
    const int warp = tid >> 5;

    __shared__ float4 q2s[128];
    __shared__ float sc[32];
    __shared__ float attn_s[32];

    if (tid < 128) q2s[tid] = g_q2[b * 128 + tid];
    __syncthreads();

    const float4* K4 = (const float4*)keys;
#pragma unroll
    for (int kk = 0; kk < 4; kk++) {
        const int k = warp * 4 + kk;
        const long base = ((long)b * K_SZ + k) * 128;
        float s = 0.f;
#pragma unroll
        for (int i = 0; i < 4; i++) {
            float4 kv = K4[base + i * 32 + lane];
            float4 qv = q2s[i * 32 + lane];
            s = fmaf(kv.x, qv.x, s);
            s = fmaf(kv.y, qv.y, s);
            s = fmaf(kv.z, qv.z, s);
            s = fmaf(kv.w, qv.w, s);
        }
#pragma unroll
        for (int off = 16; off; off >>= 1)
            s += __shfl_xor_sync(0xffffffffu, s, off);
        if (lane == 0) sc[k] = s * 0.044194173824159216f;  // 1/sqrt(512)
    }
    __syncthreads();

    if (tid < 32) {
        float s = sc[tid];
        float m = s;
#pragma unroll
        for (int off = 16; off; off >>= 1)
            m = fmaxf(m, __shfl_xor_sync(0xffffffffu, m, off));
        float p = __expf(s - m);
        float sum = p;
#pragma unroll
        for (int off = 16; off; off >>= 1)
            sum += __shfl_xor_sync(0xffffffffu, sum, off);
        attn_s[tid] = p / sum;
    }
    __syncthreads();

    const float2* V2 = (const float2*)values;
    const float2* X2 = (const float2*)x;
    float2 acc = make_float2(0.f, 0.f);
    const long vbase = (long)b * K_SZ * 256;
#pragma unroll
    for (int k = 0; k < K_SZ; k++) {
        const float a = attn_s[k];
        float2 v = V2[vbase + k * 256 + tid];
        acc.x = fmaf(a, v.x, acc.x);
        acc.y = fmaf(a, v.y, acc.y);
    }
    float2 xv = X2[(long)b * 256 + tid];
    float2 o;
    o.x = 0.5f * xv.x + 0.5f * acc.x;
    o.y = 0.5f * xv.y + 0.5f * acc.y;
    ((float2*)out)[(long)b * 256 + tid] = o;
}

// ---------------------------------------------------------------------------
extern "C" void kernel_launch(void* const* d_in, const int* in_sizes, int n_in,
                              void* d_out, int out_size) {
    (void)in_sizes; (void)n_in; (void)out_size;
    const float* x      = (const float*)d_in[0];
    const float* keys   = (const float*)d_in[1];
    const float* values = (const float*)d_in[2];
    const float* w1     = (const float*)d_in[3];
    const float* b1     = (const float*)d_in[4];
    const float* w2     = (const float*)d_in[5];
    // d_in[6] = b2: per-row constant in scores -> cancels in softmax.
    float* out = (float*)d_out;

    static cudaStream_t s2 = nullptr;
    static cudaEvent_t evRoot = nullptr, evSplit = nullptr, evPart = nullptr,
                       evG2 = nullptr, evJoin = nullptr;
    if (!s2) {
        cudaStreamCreateWithFlags(&s2, cudaStreamNonBlocking);
        cudaEventCreateWithFlags(&evRoot, cudaEventDisableTiming);
        cudaEventCreateWithFlags(&evSplit, cudaEventDisableTiming);
        cudaEventCreateWithFlags(&evPart, cudaEventDisableTiming);
        cudaEventCreateWithFlags(&evG2, cudaEventDisableTiming);
        cudaEventCreateWithFlags(&evJoin, cudaEventDisableTiming);
    }

    const int gemm_smem = 9 * SA_HALVES * (int)sizeof(__nv_bfloat16);  // 92160
    cudaFuncSetAttribute(gemm_mma_kernel,
                         cudaFuncAttributeMaxDynamicSharedMemorySize, gemm_smem);

    // Fork s2 off the main (captured) stream.
    cudaEventRecord(evRoot, 0);
    cudaStreamWaitEvent(s2, evRoot, 0);

    // s2: split_x (independent of the M-chain)
    split_x_kernel<<<4096, 256, 0, s2>>>(x, b1, w2);
    cudaEventRecord(evSplit, s2);

    // main: M-chain
    compute_M_part_kernel<<<dim3(8, 8, 8), 256>>>(w1, w2);
    reduce_split_kernel<<<256, 256>>>();

    // main: split-K lead chunk (rows 0..2047, 4 k-slices -> partials)
    cudaStreamWaitEvent(0, evSplit, 0);
    gemm_mma_kernel<<<dim3(4, 16, 4), 256, gemm_smem>>>(0, 1);
    cudaEventRecord(evPart, 0);

    // main: bulk gemm (rows 2048..8191, full k, bias)
    gemm_mma_kernel<<<dim3(4, 48), 256, gemm_smem>>>(16, 0);
    cudaEventRecord(evG2, 0);

    // s2: reduce lead-chunk partials, then attention chunks
    cudaStreamWaitEvent(s2, evPart, 0);
    reduce_q1_kernel<<<1024, 256, 0, s2>>>();
    attn_kernel<<<Q1ROWS, 256, 0, s2>>>(x, keys, values, out, 0);
    cudaStreamWaitEvent(s2, evG2, 0);
    attn_kernel<<<B_SZ - Q1ROWS, 256, 0, s2>>>(x, keys, values, out, Q1ROWS);

    // Join s2 back into the captured stream.
    cudaEventRecord(evJoin, s2);
    cudaStreamWaitEvent(0, evJoin, 0);
}